// round 1
// baseline (speedup 1.0000x reference)
#include <cuda_runtime.h>

// Problem constants
#define BB   2
#define SS   2048
#define DD   1024
#define HH   16
#define HD   64
#define MTOT (BB*SS)   // 4096

// Scratch (allocation-free: __device__ globals)
__device__ float g_Q[MTOT*DD];
__device__ float g_K[MTOT*DD];
__device__ float g_V[MTOT*DD];
__device__ float g_C[MTOT*DD];

// ---------------------------------------------------------------------------
// C[M,N] = A[M,K] @ W[N,K]^T   (both row-major, K contiguous)
// 128x128 tile, BK=16, 256 threads, 8x8 per-thread accumulators.
// ---------------------------------------------------------------------------
__global__ __launch_bounds__(256, 2)
void gemm_nt(const float* __restrict__ A, const float* __restrict__ W,
             float* __restrict__ C, int M, int N, int K)
{
    __shared__ float As[16][128];
    __shared__ float Bs[16][128];

    const int tid = threadIdx.x;
    const int tx  = tid & 15;
    const int ty  = tid >> 4;
    const int tx4 = tx << 2;
    const int ty4 = ty << 2;
    const int m0  = blockIdx.y << 7;
    const int n0  = blockIdx.x << 7;

    const float* Ap = A + (size_t)m0 * K;
    const float* Wp = W + (size_t)n0 * K;

    float acc[8][8];
#pragma unroll
    for (int i = 0; i < 8; i++)
#pragma unroll
        for (int j = 0; j < 8; j++) acc[i][j] = 0.f;

    for (int kt = 0; kt < K; kt += 16) {
        __syncthreads();
#pragma unroll
        for (int u = 0; u < 2; u++) {
            int idx = tid + (u << 8);      // 0..511
            int row = idx >> 2;            // 0..127
            int c4  = (idx & 3) << 2;      // 0,4,8,12
            float4 av = *reinterpret_cast<const float4*>(Ap + (size_t)row * K + kt + c4);
            As[c4 + 0][row] = av.x;
            As[c4 + 1][row] = av.y;
            As[c4 + 2][row] = av.z;
            As[c4 + 3][row] = av.w;
            float4 wv = *reinterpret_cast<const float4*>(Wp + (size_t)row * K + kt + c4);
            Bs[c4 + 0][row] = wv.x;
            Bs[c4 + 1][row] = wv.y;
            Bs[c4 + 2][row] = wv.z;
            Bs[c4 + 3][row] = wv.w;
        }
        __syncthreads();
#pragma unroll
        for (int kk = 0; kk < 16; kk++) {
            float a[8], b[8];
            *reinterpret_cast<float4*>(&a[0]) = *reinterpret_cast<float4*>(&As[kk][ty4]);
            *reinterpret_cast<float4*>(&a[4]) = *reinterpret_cast<float4*>(&As[kk][64 + ty4]);
            *reinterpret_cast<float4*>(&b[0]) = *reinterpret_cast<float4*>(&Bs[kk][tx4]);
            *reinterpret_cast<float4*>(&b[4]) = *reinterpret_cast<float4*>(&Bs[kk][64 + tx4]);
#pragma unroll
            for (int i = 0; i < 8; i++)
#pragma unroll
                for (int j = 0; j < 8; j++)
                    acc[i][j] = fmaf(a[i], b[j], acc[i][j]);
        }
    }

#pragma unroll
    for (int ii = 0; ii < 2; ii++)
#pragma unroll
        for (int i = 0; i < 4; i++) {
            int m = m0 + ii * 64 + ty4 + i;
            float* Cr = C + (size_t)m * N + n0;
            float4 v0 = make_float4(acc[ii*4+i][0], acc[ii*4+i][1], acc[ii*4+i][2], acc[ii*4+i][3]);
            float4 v1 = make_float4(acc[ii*4+i][4], acc[ii*4+i][5], acc[ii*4+i][6], acc[ii*4+i][7]);
            *reinterpret_cast<float4*>(Cr + tx4)      = v0;
            *reinterpret_cast<float4*>(Cr + 64 + tx4) = v1;
        }
}

// ---------------------------------------------------------------------------
// Flash attention, fp32. One block = (b, h, 64-row Q tile). 256 threads (16x16).
// Smem: Qs/Ks transposed [d][row], Vs natural [row][d], Ps [q][k]; stride 68.
// ---------------------------------------------------------------------------
#define PST 68

__global__ __launch_bounds__(256)
void attn(const float* __restrict__ Q, const float* __restrict__ Kg,
          const float* __restrict__ V, const float* __restrict__ mask,
          float* __restrict__ ctx)
{
    extern __shared__ float sm[];
    float* Qs = sm;              // [64][68]  Qs[d][q]
    float* Ks = Qs + 64 * PST;   // [64][68]  Ks[d][k]
    float* Vs = Ks + 64 * PST;   // [64][68]  Vs[k][d]
    float* Ps = Vs + 64 * PST;   // [64][68]  Ps[q][k]

    const int tid = threadIdx.x;
    const int tx  = tid & 15;
    const int ty  = tid >> 4;
    const int tx4 = tx << 2;
    const int ty4 = ty << 2;
    const int qt = blockIdx.x;
    const int h  = blockIdx.y;
    const int b  = blockIdx.z;

    const int q0   = b * SS + qt * 64;   // row into [MTOT, DD]
    const int col0 = h * HD;
    const float scale = 0.03125f;        // 1/sqrt(1024)

    // Load Q tile transposed
#pragma unroll
    for (int u = 0; u < 4; u++) {
        int idx = tid + (u << 8);        // 0..1023
        int r   = idx >> 4;              // 0..63
        int c4  = (idx & 15) << 2;       // 0..60
        float4 v = *reinterpret_cast<const float4*>(Q + (size_t)(q0 + r) * DD + col0 + c4);
        Qs[(c4 + 0) * PST + r] = v.x;
        Qs[(c4 + 1) * PST + r] = v.y;
        Qs[(c4 + 2) * PST + r] = v.z;
        Qs[(c4 + 3) * PST + r] = v.w;
    }

    float mrow[4], lrow[4], O[4][4];
#pragma unroll
    for (int i = 0; i < 4; i++) {
        mrow[i] = -1e30f;
        lrow[i] = 0.f;
#pragma unroll
        for (int j = 0; j < 4; j++) O[i][j] = 0.f;
    }

    for (int t = 0; t < SS / 64; t++) {
        const int k0 = b * SS + t * 64;
        __syncthreads();
#pragma unroll
        for (int u = 0; u < 4; u++) {
            int idx = tid + (u << 8);
            int r   = idx >> 4;
            int c4  = (idx & 15) << 2;
            float4 kv = *reinterpret_cast<const float4*>(Kg + (size_t)(k0 + r) * DD + col0 + c4);
            Ks[(c4 + 0) * PST + r] = kv.x;
            Ks[(c4 + 1) * PST + r] = kv.y;
            Ks[(c4 + 2) * PST + r] = kv.z;
            Ks[(c4 + 3) * PST + r] = kv.w;
            float4 vv = *reinterpret_cast<const float4*>(V + (size_t)(k0 + r) * DD + col0 + c4);
            *reinterpret_cast<float4*>(&Vs[r * PST + c4]) = vv;
        }
        __syncthreads();

        // S = Q K^T  (this thread: q rows ty4..ty4+3, k cols tx4..tx4+3)
        float s[4][4];
#pragma unroll
        for (int i = 0; i < 4; i++)
#pragma unroll
            for (int j = 0; j < 4; j++) s[i][j] = 0.f;

#pragma unroll 8
        for (int d = 0; d < 64; d++) {
            float4 qv = *reinterpret_cast<float4*>(&Qs[d * PST + ty4]);
            float4 kv = *reinterpret_cast<float4*>(&Ks[d * PST + tx4]);
            float qa[4] = {qv.x, qv.y, qv.z, qv.w};
            float ka[4] = {kv.x, kv.y, kv.z, kv.w};
#pragma unroll
            for (int i = 0; i < 4; i++)
#pragma unroll
                for (int j = 0; j < 4; j++)
                    s[i][j] = fmaf(qa[i], ka[j], s[i][j]);
        }

        // mask + scale, online softmax stats, write P
        float alpha[4];
#pragma unroll
        for (int i = 0; i < 4; i++) {
            float4 mk = *reinterpret_cast<const float4*>(
                mask + (size_t)(qt * 64 + ty4 + i) * SS + t * 64 + tx4);
            s[i][0] = (s[i][0] + mk.x) * scale;
            s[i][1] = (s[i][1] + mk.y) * scale;
            s[i][2] = (s[i][2] + mk.z) * scale;
            s[i][3] = (s[i][3] + mk.w) * scale;

            float mt = fmaxf(fmaxf(s[i][0], s[i][1]), fmaxf(s[i][2], s[i][3]));
#pragma unroll
            for (int off = 8; off > 0; off >>= 1)
                mt = fmaxf(mt, __shfl_xor_sync(0xffffffffu, mt, off));
            float mn = fmaxf(mrow[i], mt);
            alpha[i] = __expf(mrow[i] - mn);

            float rs = 0.f;
#pragma unroll
            for (int j = 0; j < 4; j++) {
                s[i][j] = __expf(s[i][j] - mn);
                rs += s[i][j];
            }
#pragma unroll
            for (int off = 8; off > 0; off >>= 1)
                rs += __shfl_xor_sync(0xffffffffu, rs, off);

            lrow[i] = lrow[i] * alpha[i] + rs;
            mrow[i] = mn;
            *reinterpret_cast<float4*>(&Ps[(ty4 + i) * PST + tx4]) =
                make_float4(s[i][0], s[i][1], s[i][2], s[i][3]);
        }
        __syncthreads();

        // O = alpha*O + P @ V   (this thread: q rows ty4..+3, d cols tx4..+3)
#pragma unroll
        for (int i = 0; i < 4; i++)
#pragma unroll
            for (int j = 0; j < 4; j++) O[i][j] *= alpha[i];

#pragma unroll 4
        for (int kj = 0; kj < 64; kj++) {
            float4 vv = *reinterpret_cast<float4*>(&Vs[kj * PST + tx4]);
#pragma unroll
            for (int i = 0; i < 4; i++) {
                float p = Ps[(ty4 + i) * PST + kj];
                O[i][0] = fmaf(p, vv.x, O[i][0]);
                O[i][1] = fmaf(p, vv.y, O[i][1]);
                O[i][2] = fmaf(p, vv.z, O[i][2]);
                O[i][3] = fmaf(p, vv.w, O[i][3]);
            }
        }
    }

    // normalize + store context [B,S,D]
#pragma unroll
    for (int i = 0; i < 4; i++) {
        float inv = 1.0f / lrow[i];
        float4 ov = make_float4(O[i][0] * inv, O[i][1] * inv, O[i][2] * inv, O[i][3] * inv);
        *reinterpret_cast<float4*>(ctx + (size_t)(q0 + ty4 + i) * DD + col0 + tx4) = ov;
    }
}

// ---------------------------------------------------------------------------
extern "C" void kernel_launch(void* const* d_in, const int* in_sizes, int n_in,
                              void* d_out, int out_size)
{
    const float* x    = (const float*)d_in[0];
    const float* mask = (const float*)d_in[1];
    const float* Wq   = (const float*)d_in[2];
    const float* Wk   = (const float*)d_in[3];
    const float* Wv   = (const float*)d_in[4];
    const float* Wo   = (const float*)d_in[5];
    float* out = (float*)d_out;

    float *pQ, *pK, *pV, *pC;
    cudaGetSymbolAddress((void**)&pQ, g_Q);
    cudaGetSymbolAddress((void**)&pK, g_K);
    cudaGetSymbolAddress((void**)&pV, g_V);
    cudaGetSymbolAddress((void**)&pC, g_C);

    dim3 gblk(256);
    dim3 ggrid(DD / 128, MTOT / 128);   // (8, 32)

    gemm_nt<<<ggrid, gblk>>>(x, Wq, pQ, MTOT, DD, DD);
    gemm_nt<<<ggrid, gblk>>>(x, Wk, pK, MTOT, DD, DD);
    gemm_nt<<<ggrid, gblk>>>(x, Wv, pV, MTOT, DD, DD);

    int smem = 4 * 64 * PST * sizeof(float);  // 69632 B
    cudaFuncSetAttribute(attn, cudaFuncAttributeMaxDynamicSharedMemorySize, smem);
    dim3 agrid(SS / 64, HH, BB);              // (32, 16, 2)
    attn<<<agrid, gblk, smem>>>(pQ, pK, pV, mask, pC);

    gemm_nt<<<ggrid, gblk>>>(pC, Wo, out, MTOT, DD, DD);
}

// round 4
// speedup vs baseline: 2.2311x; 2.2311x over previous
#include <cuda_runtime.h>
#include <cstdint>

// Problem constants
#define BB   2
#define SS   2048
#define DD   1024
#define HH   16
#define HD   64
#define MTOT (BB*SS)   // 4096
#define GK   1024

// Scratch (allocation-free: __device__ globals)
__device__ float g_Q[MTOT*DD];
__device__ float g_K[MTOT*DD];
__device__ float g_V[MTOT*DD];
__device__ float g_C[MTOT*DD];

// ---------------------------------------------------------------------------
// tf32 helpers (base-ISA, sm_80+: compiles for compute_103)
// ---------------------------------------------------------------------------
__device__ __forceinline__ uint32_t f2tf32(float f) {
    uint32_t r;
    asm("cvt.rna.tf32.f32 %0, %1;" : "=r"(r) : "f"(f));
    return r;
}

// D = A*B + C, m16n8k8, A row-major tf32, B col-major tf32, C/D fp32
__device__ __forceinline__ void mma_tf32(float* c, const uint32_t* a, const uint32_t* b) {
    asm volatile(
        "mma.sync.aligned.m16n8k8.row.col.f32.tf32.tf32.f32 "
        "{%0,%1,%2,%3}, {%4,%5,%6,%7}, {%8,%9}, {%0,%1,%2,%3};"
        : "+f"(c[0]), "+f"(c[1]), "+f"(c[2]), "+f"(c[3])
        : "r"(a[0]), "r"(a[1]), "r"(a[2]), "r"(a[3]), "r"(b[0]), "r"(b[1]));
}

__device__ __forceinline__ uint32_t fbits(float f) { return __float_as_uint(f); }

// ===========================================================================
// GEMM: C[M,N] = A[M,K] @ W[N,K]^T, K=1024. mma.sync tf32.
// CTA 128x128, BK=32, 8 warps in 2(m) x 4(n); per warp 64x32 = 4x4 mma tiles.
// Smem stride 36 floats (36 mod 32 = 4 -> conflict-free fragment loads).
// ===========================================================================
#define GST   36
#define GSTG  (128*GST)          // floats per A (or B) tile
#define GEMM_SMEM (4*GSTG*4)     // 2 stages * (A+B) * 4B = 73728 B

__global__ __launch_bounds__(256, 1)
void gemm_mma(const float* __restrict__ A, const float* __restrict__ W,
              float* __restrict__ C, int M, int N)
{
    extern __shared__ float sm[];
    // stage s: A at s*2*GSTG, B at s*2*GSTG + GSTG

    const int tid  = threadIdx.x;
    const int wid  = tid >> 5;
    const int lane = tid & 31;
    const int gp   = lane >> 2;    // groupID 0..7
    const int tg   = lane & 3;     // threadID_in_group 0..3
    const int wr   = wid & 1;      // warp m (0..1) -> 64 rows
    const int wc   = wid >> 1;     // warp n (0..3) -> 32 cols
    const int m0   = blockIdx.y << 7;
    const int n0   = blockIdx.x << 7;

    const float* Ap = A + (size_t)m0 * GK;
    const float* Wp = W + (size_t)n0 * GK;

    // staging map: idx = tid + u*256 in [0,1024): row = idx>>3, col4 = (idx&7)*4
    int srow[4], sc4[4];
#pragma unroll
    for (int u = 0; u < 4; u++) {
        int idx = tid + (u << 8);
        srow[u] = idx >> 3;
        sc4[u]  = (idx & 7) << 2;
    }

    float acc[16][4];
#pragma unroll
    for (int i = 0; i < 16; i++)
#pragma unroll
        for (int j = 0; j < 4; j++) acc[i][j] = 0.f;

    float4 pa[4], pb[4];

    // prologue: chunk 0 -> regs -> stage 0
#pragma unroll
    for (int u = 0; u < 4; u++) {
        pa[u] = *reinterpret_cast<const float4*>(Ap + (size_t)srow[u] * GK + sc4[u]);
        pb[u] = *reinterpret_cast<const float4*>(Wp + (size_t)srow[u] * GK + sc4[u]);
    }
#pragma unroll
    for (int u = 0; u < 4; u++) {
        float* da = sm + srow[u] * GST + sc4[u];
        float* db = sm + GSTG + srow[u] * GST + sc4[u];
        da[0] = __uint_as_float(f2tf32(pa[u].x)); da[1] = __uint_as_float(f2tf32(pa[u].y));
        da[2] = __uint_as_float(f2tf32(pa[u].z)); da[3] = __uint_as_float(f2tf32(pa[u].w));
        db[0] = __uint_as_float(f2tf32(pb[u].x)); db[1] = __uint_as_float(f2tf32(pb[u].y));
        db[2] = __uint_as_float(f2tf32(pb[u].z)); db[3] = __uint_as_float(f2tf32(pb[u].w));
    }
    __syncthreads();

    const int NCH = GK / 32;   // 32
    for (int i = 0; i < NCH; i++) {
        const int b = i & 1;

        // prefetch next chunk to regs (overlaps with mma)
        if (i + 1 < NCH) {
            const int kt = (i + 1) << 5;
#pragma unroll
            for (int u = 0; u < 4; u++) {
                pa[u] = *reinterpret_cast<const float4*>(Ap + (size_t)srow[u] * GK + kt + sc4[u]);
                pb[u] = *reinterpret_cast<const float4*>(Wp + (size_t)srow[u] * GK + kt + sc4[u]);
            }
        }

        // compute 4 k-steps on stage b
        const float* As = sm + b * 2 * GSTG;
        const float* Bs = As + GSTG;
#pragma unroll
        for (int kk = 0; kk < 4; kk++) {
            uint32_t af[4][4], bf[4][2];
#pragma unroll
            for (int tm = 0; tm < 4; tm++) {
                const float* p = As + (wr * 64 + tm * 16 + gp) * GST + kk * 8 + tg;
                af[tm][0] = fbits(p[0]);
                af[tm][1] = fbits(p[8 * GST]);
                af[tm][2] = fbits(p[4]);
                af[tm][3] = fbits(p[8 * GST + 4]);
            }
#pragma unroll
            for (int tn = 0; tn < 4; tn++) {
                const float* p = Bs + (wc * 32 + tn * 8 + gp) * GST + kk * 8 + tg;
                bf[tn][0] = fbits(p[0]);
                bf[tn][1] = fbits(p[4]);
            }
#pragma unroll
            for (int tm = 0; tm < 4; tm++)
#pragma unroll
                for (int tn = 0; tn < 4; tn++)
                    mma_tf32(acc[tm * 4 + tn], af[tm], bf[tn]);
        }

        // stage next chunk into the other buffer
        if (i + 1 < NCH) {
            float* da0 = sm + (b ^ 1) * 2 * GSTG;
            float* db0 = da0 + GSTG;
#pragma unroll
            for (int u = 0; u < 4; u++) {
                float* da = da0 + srow[u] * GST + sc4[u];
                float* db = db0 + srow[u] * GST + sc4[u];
                da[0] = __uint_as_float(f2tf32(pa[u].x)); da[1] = __uint_as_float(f2tf32(pa[u].y));
                da[2] = __uint_as_float(f2tf32(pa[u].z)); da[3] = __uint_as_float(f2tf32(pa[u].w));
                db[0] = __uint_as_float(f2tf32(pb[u].x)); db[1] = __uint_as_float(f2tf32(pb[u].y));
                db[2] = __uint_as_float(f2tf32(pb[u].z)); db[3] = __uint_as_float(f2tf32(pb[u].w));
            }
        }
        __syncthreads();
    }

    // epilogue: C[row][col], c0/c1 at (gp, 2tg/2tg+1), c2/c3 at (gp+8, ...)
#pragma unroll
    for (int tm = 0; tm < 4; tm++) {
        const int r = m0 + wr * 64 + tm * 16 + gp;
#pragma unroll
        for (int tn = 0; tn < 4; tn++) {
            const int c = n0 + wc * 32 + tn * 8 + 2 * tg;
            float* p0 = C + (size_t)r * N + c;
            float* p1 = C + (size_t)(r + 8) * N + c;
            *reinterpret_cast<float2*>(p0) = make_float2(acc[tm*4+tn][0], acc[tm*4+tn][1]);
            *reinterpret_cast<float2*>(p1) = make_float2(acc[tm*4+tn][2], acc[tm*4+tn][3]);
        }
    }
}

// ===========================================================================
// Flash attention with mma.sync tf32.
// Block: 256 thr (8 warps), Q tile 128 rows (16 per warp), K tiles of 64.
// Smem stride 68 (68 mod 32 = 4 -> conflict-free fragment loads).
// ===========================================================================
#define AST     68
#define QS_OFF  0
#define KS_OFF  (128*AST)            // 8704
#define VS_OFF  (KS_OFF + 64*AST)    // 13056
#define PS_OFF  (VS_OFF + 64*AST)    // 17408
#define ATTN_SMEM ((PS_OFF + 128*AST)*4)   // 104448 B

__global__ __launch_bounds__(256, 1)
void attn_mma(const float* __restrict__ Q, const float* __restrict__ Kg,
              const float* __restrict__ V, const float* __restrict__ mask,
              float* __restrict__ ctx)
{
    extern __shared__ float sm[];
    float* Qs = sm + QS_OFF;
    float* Ks = sm + KS_OFF;
    float* Vs = sm + VS_OFF;
    float* Ps = sm + PS_OFF;

    const int tid  = threadIdx.x;
    const int wid  = tid >> 5;
    const int lane = tid & 31;
    const int gp   = lane >> 2;
    const int tg   = lane & 3;

    const int qt = blockIdx.x;   // 0..15
    const int h  = blockIdx.y;
    const int b  = blockIdx.z;

    const int q0g  = b * SS + qt * 128;   // row into [MTOT, DD]
    const int col0 = h * HD;
    const float scale = 0.03125f;         // 1/sqrt(1024)

    // --- stage Q tile (128 x 64) as tf32
#pragma unroll
    for (int u = 0; u < 8; u++) {
        int idx = tid + (u << 8);         // 0..2047
        int r   = idx >> 4;               // 0..127
        int c4  = (idx & 15) << 2;        // 0..60
        float4 v = *reinterpret_cast<const float4*>(Q + (size_t)(q0g + r) * DD + col0 + c4);
        float* d = Qs + r * AST + c4;
        d[0] = __uint_as_float(f2tf32(v.x)); d[1] = __uint_as_float(f2tf32(v.y));
        d[2] = __uint_as_float(f2tf32(v.z)); d[3] = __uint_as_float(f2tf32(v.w));
    }

    float mprev0 = -1e30f, mprev1 = -1e30f;
    float lsum0 = 0.f, lsum1 = 0.f;
    float O[8][4];
#pragma unroll
    for (int i = 0; i < 8; i++)
#pragma unroll
        for (int j = 0; j < 4; j++) O[i][j] = 0.f;

    const int qm0 = wid * 16;   // warp's q-row base within tile
    const float* mrow0 = mask + (size_t)(qt * 128 + qm0 + gp) * SS;
    const float* mrow1 = mrow0 + 8 * SS;

    for (int t = 0; t < SS / 64; t++) {
        const int k0 = b * SS + t * 64;
        __syncthreads();
        // --- stage K,V tiles (64 x 64) as tf32
#pragma unroll
        for (int u = 0; u < 4; u++) {
            int idx = tid + (u << 8);
            int r   = idx >> 4;
            int c4  = (idx & 15) << 2;
            float4 kv = *reinterpret_cast<const float4*>(Kg + (size_t)(k0 + r) * DD + col0 + c4);
            float4 vv = *reinterpret_cast<const float4*>(V  + (size_t)(k0 + r) * DD + col0 + c4);
            float* dk = Ks + r * AST + c4;
            float* dv = Vs + r * AST + c4;
            dk[0] = __uint_as_float(f2tf32(kv.x)); dk[1] = __uint_as_float(f2tf32(kv.y));
            dk[2] = __uint_as_float(f2tf32(kv.z)); dk[3] = __uint_as_float(f2tf32(kv.w));
            dv[0] = __uint_as_float(f2tf32(vv.x)); dv[1] = __uint_as_float(f2tf32(vv.y));
            dv[2] = __uint_as_float(f2tf32(vv.z)); dv[3] = __uint_as_float(f2tf32(vv.w));
        }
        __syncthreads();

        // --- S = Q K^T : M=16 (warp rows), N=64, K=64
        float sacc[8][4];
#pragma unroll
        for (int nt = 0; nt < 8; nt++)
#pragma unroll
            for (int j = 0; j < 4; j++) sacc[nt][j] = 0.f;

#pragma unroll
        for (int kk = 0; kk < 8; kk++) {
            uint32_t af[4];
            const float* pq = Qs + (qm0 + gp) * AST + kk * 8 + tg;
            af[0] = fbits(pq[0]);
            af[1] = fbits(pq[8 * AST]);
            af[2] = fbits(pq[4]);
            af[3] = fbits(pq[8 * AST + 4]);
#pragma unroll
            for (int nt = 0; nt < 8; nt++) {
                uint32_t bf[2];
                const float* pk = Ks + (nt * 8 + gp) * AST + kk * 8 + tg;
                bf[0] = fbits(pk[0]);
                bf[1] = fbits(pk[4]);
                mma_tf32(sacc[nt], af, bf);
            }
        }

        // --- mask + scale, online softmax (rows r0=gp, r1=gp+8 of warp tile)
        float mx0 = -1e30f, mx1 = -1e30f;
#pragma unroll
        for (int nt = 0; nt < 8; nt++) {
            const int kc = t * 64 + nt * 8 + 2 * tg;
            float2 mk0 = *reinterpret_cast<const float2*>(mrow0 + kc);
            float2 mk1 = *reinterpret_cast<const float2*>(mrow1 + kc);
            sacc[nt][0] = (sacc[nt][0] + mk0.x) * scale;
            sacc[nt][1] = (sacc[nt][1] + mk0.y) * scale;
            sacc[nt][2] = (sacc[nt][2] + mk1.x) * scale;
            sacc[nt][3] = (sacc[nt][3] + mk1.y) * scale;
            mx0 = fmaxf(mx0, fmaxf(sacc[nt][0], sacc[nt][1]));
            mx1 = fmaxf(mx1, fmaxf(sacc[nt][2], sacc[nt][3]));
        }
#pragma unroll
        for (int off = 1; off <= 2; off <<= 1) {
            mx0 = fmaxf(mx0, __shfl_xor_sync(0xffffffffu, mx0, off));
            mx1 = fmaxf(mx1, __shfl_xor_sync(0xffffffffu, mx1, off));
        }
        const float mn0 = fmaxf(mprev0, mx0);
        const float mn1 = fmaxf(mprev1, mx1);
        const float al0 = __expf(mprev0 - mn0);
        const float al1 = __expf(mprev1 - mn1);
        mprev0 = mn0; mprev1 = mn1;

        float rs0 = 0.f, rs1 = 0.f;
        float* pr0 = Ps + (qm0 + gp) * AST + 2 * tg;
        float* pr1 = pr0 + 8 * AST;
#pragma unroll
        for (int nt = 0; nt < 8; nt++) {
            float p0 = __expf(sacc[nt][0] - mn0);
            float p1 = __expf(sacc[nt][1] - mn0);
            float p2 = __expf(sacc[nt][2] - mn1);
            float p3 = __expf(sacc[nt][3] - mn1);
            rs0 += p0 + p1;
            rs1 += p2 + p3;
            pr0[nt * 8 + 0] = __uint_as_float(f2tf32(p0));
            pr0[nt * 8 + 1] = __uint_as_float(f2tf32(p1));
            pr1[nt * 8 + 0] = __uint_as_float(f2tf32(p2));
            pr1[nt * 8 + 1] = __uint_as_float(f2tf32(p3));
        }
#pragma unroll
        for (int off = 1; off <= 2; off <<= 1) {
            rs0 += __shfl_xor_sync(0xffffffffu, rs0, off);
            rs1 += __shfl_xor_sync(0xffffffffu, rs1, off);
        }
        lsum0 = lsum0 * al0 + rs0;
        lsum1 = lsum1 * al1 + rs1;

        // rescale O
#pragma unroll
        for (int nt = 0; nt < 8; nt++) {
            O[nt][0] *= al0; O[nt][1] *= al0;
            O[nt][2] *= al1; O[nt][3] *= al1;
        }
        __syncwarp();

        // --- O += P V : M=16, N=64(d), K=64(keys); P from Ps (own warp rows)
#pragma unroll
        for (int kk = 0; kk < 8; kk++) {
            uint32_t af[4];
            const float* pp = Ps + (qm0 + gp) * AST + kk * 8 + tg;
            af[0] = fbits(pp[0]);
            af[1] = fbits(pp[8 * AST]);
            af[2] = fbits(pp[4]);
            af[3] = fbits(pp[8 * AST + 4]);
#pragma unroll
            for (int nt = 0; nt < 8; nt++) {
                uint32_t bf[2];
                const float* pv = Vs + (kk * 8 + tg) * AST + nt * 8 + gp;
                bf[0] = fbits(pv[0]);
                bf[1] = fbits(pv[4 * AST]);
                mma_tf32(O[nt], af, bf);
            }
        }
        __syncwarp();
    }

    // --- normalize + store context
    const float inv0 = 1.0f / lsum0;
    const float inv1 = 1.0f / lsum1;
    const int r0 = q0g + qm0 + gp;
#pragma unroll
    for (int nt = 0; nt < 8; nt++) {
        const int c = col0 + nt * 8 + 2 * tg;
        *reinterpret_cast<float2*>(ctx + (size_t)r0 * DD + c) =
            make_float2(O[nt][0] * inv0, O[nt][1] * inv0);
        *reinterpret_cast<float2*>(ctx + (size_t)(r0 + 8) * DD + c) =
            make_float2(O[nt][2] * inv1, O[nt][3] * inv1);
    }
}

// ---------------------------------------------------------------------------
extern "C" void kernel_launch(void* const* d_in, const int* in_sizes, int n_in,
                              void* d_out, int out_size)
{
    const float* x    = (const float*)d_in[0];
    const float* mask = (const float*)d_in[1];
    const float* Wq   = (const float*)d_in[2];
    const float* Wk   = (const float*)d_in[3];
    const float* Wv   = (const float*)d_in[4];
    const float* Wo   = (const float*)d_in[5];
    float* out = (float*)d_out;

    float *pQ, *pK, *pV, *pC;
    cudaGetSymbolAddress((void**)&pQ, g_Q);
    cudaGetSymbolAddress((void**)&pK, g_K);
    cudaGetSymbolAddress((void**)&pV, g_V);
    cudaGetSymbolAddress((void**)&pC, g_C);

    cudaFuncSetAttribute(gemm_mma, cudaFuncAttributeMaxDynamicSharedMemorySize, GEMM_SMEM);
    cudaFuncSetAttribute(attn_mma, cudaFuncAttributeMaxDynamicSharedMemorySize, ATTN_SMEM);

    dim3 blk(256);
    dim3 ggrid(DD / 128, MTOT / 128);   // (8, 32)

    gemm_mma<<<ggrid, blk, GEMM_SMEM>>>(x, Wq, pQ, MTOT, DD);
    gemm_mma<<<ggrid, blk, GEMM_SMEM>>>(x, Wk, pK, MTOT, DD);
    gemm_mma<<<ggrid, blk, GEMM_SMEM>>>(x, Wv, pV, MTOT, DD);

    dim3 agrid(SS / 128, HH, BB);       // (16, 16, 2)
    attn_mma<<<agrid, blk, ATTN_SMEM>>>(pQ, pK, pV, mask, pC);

    gemm_mma<<<ggrid, blk, GEMM_SMEM>>>(pC, Wo, out, MTOT, DD);
}

// round 5
// speedup vs baseline: 2.7083x; 1.2139x over previous
#include <cuda_runtime.h>
#include <cstdint>

// Problem constants
#define BB   2
#define SS   2048
#define DD   1024
#define HH   16
#define HD   64
#define MTOT (BB*SS)   // 4096
#define GK   1024

// Scratch (allocation-free: __device__ globals)
__device__ float g_Q[MTOT*DD];
__device__ float g_K[MTOT*DD];
__device__ float g_V[MTOT*DD];
__device__ float g_C[MTOT*DD];

// ---------------------------------------------------------------------------
// helpers
// ---------------------------------------------------------------------------
__device__ __forceinline__ uint32_t f2tf32(float f) {
    uint32_t r;
    asm("cvt.rna.tf32.f32 %0, %1;" : "=r"(r) : "f"(f));
    return r;
}
__device__ __forceinline__ void mma_tf32(float* c, const uint32_t* a, const uint32_t* b) {
    asm volatile(
        "mma.sync.aligned.m16n8k8.row.col.f32.tf32.tf32.f32 "
        "{%0,%1,%2,%3}, {%4,%5,%6,%7}, {%8,%9}, {%0,%1,%2,%3};"
        : "+f"(c[0]), "+f"(c[1]), "+f"(c[2]), "+f"(c[3])
        : "r"(a[0]), "r"(a[1]), "r"(a[2]), "r"(a[3]), "r"(b[0]), "r"(b[1]));
}
__device__ __forceinline__ uint32_t fbits(float f) { return __float_as_uint(f); }

__device__ __forceinline__ uint32_t smem_u32(const void* p) {
    uint32_t a;
    asm("{ .reg .u64 t; cvta.to.shared.u64 t, %1; cvt.u32.u64 %0, t; }"
        : "=r"(a) : "l"(p));
    return a;
}
#define CP16(dst, src) \
    asm volatile("cp.async.ca.shared.global [%0], [%1], 16;" \
                 :: "r"(dst), "l"(src) : "memory")
#define CP_COMMIT() asm volatile("cp.async.commit_group;" ::: "memory")
#define CP_WAIT1()  asm volatile("cp.async.wait_group 1;" ::: "memory")
#define CP_WAIT0()  asm volatile("cp.async.wait_group 0;" ::: "memory")

// ===========================================================================
// GEMM: C[M,N] = A[M,K] @ W[N,K]^T, K=1024. mma.sync tf32. (as R3, proven)
// ===========================================================================
#define GST   36
#define GSTG  (128*GST)
#define GEMM_SMEM (4*GSTG*4)     // 73728 B

__device__ __forceinline__
void gemm_body(const float* __restrict__ A, const float* __restrict__ W,
               float* __restrict__ C, int N, float* sm)
{
    const int tid  = threadIdx.x;
    const int wid  = tid >> 5;
    const int lane = tid & 31;
    const int gp   = lane >> 2;
    const int tg   = lane & 3;
    const int wr   = wid & 1;
    const int wc   = wid >> 1;
    const int m0   = blockIdx.y << 7;
    const int n0   = blockIdx.x << 7;

    const float* Ap = A + (size_t)m0 * GK;
    const float* Wp = W + (size_t)n0 * GK;

    int srow[4], sc4[4];
#pragma unroll
    for (int u = 0; u < 4; u++) {
        int idx = tid + (u << 8);
        srow[u] = idx >> 3;
        sc4[u]  = (idx & 7) << 2;
    }

    float acc[16][4];
#pragma unroll
    for (int i = 0; i < 16; i++)
#pragma unroll
        for (int j = 0; j < 4; j++) acc[i][j] = 0.f;

    float4 pa[4], pb[4];
#pragma unroll
    for (int u = 0; u < 4; u++) {
        pa[u] = *reinterpret_cast<const float4*>(Ap + (size_t)srow[u] * GK + sc4[u]);
        pb[u] = *reinterpret_cast<const float4*>(Wp + (size_t)srow[u] * GK + sc4[u]);
    }
#pragma unroll
    for (int u = 0; u < 4; u++) {
        float* da = sm + srow[u] * GST + sc4[u];
        float* db = sm + GSTG + srow[u] * GST + sc4[u];
        da[0] = __uint_as_float(f2tf32(pa[u].x)); da[1] = __uint_as_float(f2tf32(pa[u].y));
        da[2] = __uint_as_float(f2tf32(pa[u].z)); da[3] = __uint_as_float(f2tf32(pa[u].w));
        db[0] = __uint_as_float(f2tf32(pb[u].x)); db[1] = __uint_as_float(f2tf32(pb[u].y));
        db[2] = __uint_as_float(f2tf32(pb[u].z)); db[3] = __uint_as_float(f2tf32(pb[u].w));
    }
    __syncthreads();

    const int NCH = GK / 32;
    for (int i = 0; i < NCH; i++) {
        const int b = i & 1;
        if (i + 1 < NCH) {
            const int kt = (i + 1) << 5;
#pragma unroll
            for (int u = 0; u < 4; u++) {
                pa[u] = *reinterpret_cast<const float4*>(Ap + (size_t)srow[u] * GK + kt + sc4[u]);
                pb[u] = *reinterpret_cast<const float4*>(Wp + (size_t)srow[u] * GK + kt + sc4[u]);
            }
        }
        const float* As = sm + b * 2 * GSTG;
        const float* Bs = As + GSTG;
#pragma unroll
        for (int kk = 0; kk < 4; kk++) {
            uint32_t af[4][4], bf[4][2];
#pragma unroll
            for (int tm = 0; tm < 4; tm++) {
                const float* p = As + (wr * 64 + tm * 16 + gp) * GST + kk * 8 + tg;
                af[tm][0] = fbits(p[0]);
                af[tm][1] = fbits(p[8 * GST]);
                af[tm][2] = fbits(p[4]);
                af[tm][3] = fbits(p[8 * GST + 4]);
            }
#pragma unroll
            for (int tn = 0; tn < 4; tn++) {
                const float* p = Bs + (wc * 32 + tn * 8 + gp) * GST + kk * 8 + tg;
                bf[tn][0] = fbits(p[0]);
                bf[tn][1] = fbits(p[4]);
            }
#pragma unroll
            for (int tm = 0; tm < 4; tm++)
#pragma unroll
                for (int tn = 0; tn < 4; tn++)
                    mma_tf32(acc[tm * 4 + tn], af[tm], bf[tn]);
        }
        if (i + 1 < NCH) {
            float* da0 = sm + (b ^ 1) * 2 * GSTG;
            float* db0 = da0 + GSTG;
#pragma unroll
            for (int u = 0; u < 4; u++) {
                float* da = da0 + srow[u] * GST + sc4[u];
                float* db = db0 + srow[u] * GST + sc4[u];
                da[0] = __uint_as_float(f2tf32(pa[u].x)); da[1] = __uint_as_float(f2tf32(pa[u].y));
                da[2] = __uint_as_float(f2tf32(pa[u].z)); da[3] = __uint_as_float(f2tf32(pa[u].w));
                db[0] = __uint_as_float(f2tf32(pb[u].x)); db[1] = __uint_as_float(f2tf32(pb[u].y));
                db[2] = __uint_as_float(f2tf32(pb[u].z)); db[3] = __uint_as_float(f2tf32(pb[u].w));
            }
        }
        __syncthreads();
    }

#pragma unroll
    for (int tm = 0; tm < 4; tm++) {
        const int r = m0 + wr * 64 + tm * 16 + gp;
#pragma unroll
        for (int tn = 0; tn < 4; tn++) {
            const int c = n0 + wc * 32 + tn * 8 + 2 * tg;
            float* p0 = C + (size_t)r * N + c;
            float* p1 = C + (size_t)(r + 8) * N + c;
            *reinterpret_cast<float2*>(p0) = make_float2(acc[tm*4+tn][0], acc[tm*4+tn][1]);
            *reinterpret_cast<float2*>(p1) = make_float2(acc[tm*4+tn][2], acc[tm*4+tn][3]);
        }
    }
}

__global__ __launch_bounds__(256, 1)
void gemm_mma(const float* __restrict__ A, const float* __restrict__ W,
              float* __restrict__ C, int N)
{
    extern __shared__ float sm[];
    gemm_body(A, W, C, N, sm);
}

// fused Q/K/V projections: blockIdx.z selects weight + destination
__global__ __launch_bounds__(256, 1)
void gemm_qkv(const float* __restrict__ x,
              const float* __restrict__ Wq, const float* __restrict__ Wk,
              const float* __restrict__ Wv,
              float* __restrict__ Qo, float* __restrict__ Ko, float* __restrict__ Vo)
{
    extern __shared__ float sm[];
    const int z = blockIdx.z;
    const float* W = (z == 0) ? Wq : (z == 1) ? Wk : Wv;
    float* C = (z == 0) ? Qo : (z == 1) ? Ko : Vo;
    gemm_body(x, W, C, DD, sm);
}

// ===========================================================================
// Flash attention v2 (mma.sync tf32):
//  - Q fragments in registers (cvt.rna once)
//  - K/V raw fp32 via double-buffered cp.async (HMMA reads tf32 bits -> trunc)
//  - P kept in registers; accumulator->A-fragment remap via shuffles
// Smem: K stride 68 (banks gp*4+tg: all 32), V stride 72 (banks tg*8+gp: all 32)
// ===========================================================================
#define KST 68
#define VST 72
#define KB0 0
#define VB0 (64*KST)             // 4352
#define KB1 (VB0 + 64*VST)       // 8960
#define VB1 (KB1 + 64*KST)       // 13312
#define ATTN_SMEM ((VB1 + 64*VST)*4)   // 71680 B

__global__ __launch_bounds__(256, 1)
void attn_mma(const float* __restrict__ Q, const float* __restrict__ Kg,
              const float* __restrict__ V, const float* __restrict__ mask,
              float* __restrict__ ctx)
{
    extern __shared__ float sm[];
    const uint32_t sbase = smem_u32(sm);

    const int tid  = threadIdx.x;
    const int wid  = tid >> 5;
    const int lane = tid & 31;
    const int gp   = lane >> 2;
    const int tg   = lane & 3;

    const int qt = blockIdx.x;   // 0..15
    const int h  = blockIdx.y;
    const int b  = blockIdx.z;

    const int q0g  = b * SS + qt * 128;
    const int col0 = h * HD;
    const float scale = 0.03125f;

    // cp.async staging map: 1024 granules of 16B per 64x64 tile; 4 per thread
    int grow[4], gc4[4];
#pragma unroll
    for (int u = 0; u < 4; u++) {
        int g = tid + (u << 8);
        grow[u] = g >> 4;
        gc4[u]  = (g & 15) << 2;
    }

    // ---- issue tile 0 loads
    {
        const int k0 = b * SS;
#pragma unroll
        for (int u = 0; u < 4; u++) {
            const float* ks = Kg + (size_t)(k0 + grow[u]) * DD + col0 + gc4[u];
            const float* vs = V  + (size_t)(k0 + grow[u]) * DD + col0 + gc4[u];
            CP16(sbase + (KB0 + grow[u] * KST + gc4[u]) * 4, ks);
            CP16(sbase + (VB0 + grow[u] * VST + gc4[u]) * 4, vs);
        }
        CP_COMMIT();
    }

    // ---- Q fragments in registers (overlaps with async loads)
    const int qm0 = wid * 16;
    uint32_t qf[8][4];
    {
        const float* q0p = Q + (size_t)(q0g + qm0 + gp) * DD + col0;
        const float* q1p = q0p + 8 * DD;
#pragma unroll
        for (int kk = 0; kk < 8; kk++) {
            const int c = kk * 8 + tg;
            qf[kk][0] = f2tf32(q0p[c]);
            qf[kk][1] = f2tf32(q1p[c]);
            qf[kk][2] = f2tf32(q0p[c + 4]);
            qf[kk][3] = f2tf32(q1p[c + 4]);
        }
    }

    float mprev0 = -1e30f, mprev1 = -1e30f;
    float lsum0 = 0.f, lsum1 = 0.f;
    float O[8][4];
#pragma unroll
    for (int i = 0; i < 8; i++)
#pragma unroll
        for (int j = 0; j < 4; j++) O[i][j] = 0.f;

    const float* mrow0 = mask + (size_t)(qt * 128 + qm0 + gp) * SS;
    const float* mrow1 = mrow0 + 8 * SS;
    const uint32_t qbase = lane & ~3u;

    const int NT = SS / 64;   // 32
    for (int t = 0; t < NT; t++) {
        const int bsel = t & 1;

        // issue loads for t+1 into the other buffer
        if (t + 1 < NT) {
            const int k1 = b * SS + (t + 1) * 64;
            const int kb = bsel ? KB0 : KB1;
            const int vb = bsel ? VB0 : VB1;
#pragma unroll
            for (int u = 0; u < 4; u++) {
                const float* ks = Kg + (size_t)(k1 + grow[u]) * DD + col0 + gc4[u];
                const float* vs = V  + (size_t)(k1 + grow[u]) * DD + col0 + gc4[u];
                CP16(sbase + (kb + grow[u] * KST + gc4[u]) * 4, ks);
                CP16(sbase + (vb + grow[u] * VST + gc4[u]) * 4, vs);
            }
            CP_COMMIT();
            CP_WAIT1();
        } else {
            CP_WAIT0();
        }
        __syncthreads();

        const float* Ks = sm + (bsel ? KB1 : KB0);
        const float* Vs = sm + (bsel ? VB1 : VB0);

        // --- S = Q K^T
        float sacc[8][4];
#pragma unroll
        for (int nt = 0; nt < 8; nt++)
#pragma unroll
            for (int j = 0; j < 4; j++) sacc[nt][j] = 0.f;

#pragma unroll
        for (int kk = 0; kk < 8; kk++) {
#pragma unroll
            for (int nt = 0; nt < 8; nt++) {
                uint32_t bf[2];
                const float* pk = Ks + (nt * 8 + gp) * KST + kk * 8 + tg;
                bf[0] = fbits(pk[0]);
                bf[1] = fbits(pk[4]);
                mma_tf32(sacc[nt], qf[kk], bf);
            }
        }

        // --- mask + scale, online softmax
        float mx0 = -1e30f, mx1 = -1e30f;
#pragma unroll
        for (int nt = 0; nt < 8; nt++) {
            const int kc = t * 64 + nt * 8 + 2 * tg;
            float2 mk0 = *reinterpret_cast<const float2*>(mrow0 + kc);
            float2 mk1 = *reinterpret_cast<const float2*>(mrow1 + kc);
            sacc[nt][0] = (sacc[nt][0] + mk0.x) * scale;
            sacc[nt][1] = (sacc[nt][1] + mk0.y) * scale;
            sacc[nt][2] = (sacc[nt][2] + mk1.x) * scale;
            sacc[nt][3] = (sacc[nt][3] + mk1.y) * scale;
            mx0 = fmaxf(mx0, fmaxf(sacc[nt][0], sacc[nt][1]));
            mx1 = fmaxf(mx1, fmaxf(sacc[nt][2], sacc[nt][3]));
        }
#pragma unroll
        for (int off = 1; off <= 2; off <<= 1) {
            mx0 = fmaxf(mx0, __shfl_xor_sync(0xffffffffu, mx0, off));
            mx1 = fmaxf(mx1, __shfl_xor_sync(0xffffffffu, mx1, off));
        }
        const float mn0 = fmaxf(mprev0, mx0);
        const float mn1 = fmaxf(mprev1, mx1);
        const float al0 = __expf(mprev0 - mn0);
        const float al1 = __expf(mprev1 - mn1);
        mprev0 = mn0; mprev1 = mn1;

        float rs0 = 0.f, rs1 = 0.f;
#pragma unroll
        for (int nt = 0; nt < 8; nt++) {
            sacc[nt][0] = __expf(sacc[nt][0] - mn0);
            sacc[nt][1] = __expf(sacc[nt][1] - mn0);
            sacc[nt][2] = __expf(sacc[nt][2] - mn1);
            sacc[nt][3] = __expf(sacc[nt][3] - mn1);
            rs0 += sacc[nt][0] + sacc[nt][1];
            rs1 += sacc[nt][2] + sacc[nt][3];
        }
#pragma unroll
        for (int off = 1; off <= 2; off <<= 1) {
            rs0 += __shfl_xor_sync(0xffffffffu, rs0, off);
            rs1 += __shfl_xor_sync(0xffffffffu, rs1, off);
        }
        lsum0 = lsum0 * al0 + rs0;
        lsum1 = lsum1 * al1 + rs1;

#pragma unroll
        for (int nt = 0; nt < 8; nt++) {
            O[nt][0] *= al0; O[nt][1] *= al0;
            O[nt][2] *= al1; O[nt][3] *= al1;
        }

        // --- O += P V ; P fragments via in-register shuffle remap
#pragma unroll
        for (int kk = 0; kk < 8; kk++) {
            const uint32_t src0 = qbase + (tg >> 1);
            const uint32_t src2 = src0 + 2;
            float x0, x1;
            uint32_t af[4];
            x0 = __shfl_sync(0xffffffffu, sacc[kk][0], src0);
            x1 = __shfl_sync(0xffffffffu, sacc[kk][1], src0);
            af[0] = f2tf32((tg & 1) ? x1 : x0);
            x0 = __shfl_sync(0xffffffffu, sacc[kk][2], src0);
            x1 = __shfl_sync(0xffffffffu, sacc[kk][3], src0);
            af[1] = f2tf32((tg & 1) ? x1 : x0);
            x0 = __shfl_sync(0xffffffffu, sacc[kk][0], src2);
            x1 = __shfl_sync(0xffffffffu, sacc[kk][1], src2);
            af[2] = f2tf32((tg & 1) ? x1 : x0);
            x0 = __shfl_sync(0xffffffffu, sacc[kk][2], src2);
            x1 = __shfl_sync(0xffffffffu, sacc[kk][3], src2);
            af[3] = f2tf32((tg & 1) ? x1 : x0);

#pragma unroll
            for (int nt = 0; nt < 8; nt++) {
                uint32_t bf[2];
                const float* pv = Vs + (kk * 8 + tg) * VST + nt * 8 + gp;
                bf[0] = fbits(pv[0]);
                bf[1] = fbits(pv[4 * VST]);
                mma_tf32(O[nt], af, bf);
            }
        }
        __syncthreads();   // all warps done with buffer before next overwrite
    }

    // --- normalize + store
    const float inv0 = 1.0f / lsum0;
    const float inv1 = 1.0f / lsum1;
    const int r0 = q0g + qm0 + gp;
#pragma unroll
    for (int nt = 0; nt < 8; nt++) {
        const int c = col0 + nt * 8 + 2 * tg;
        *reinterpret_cast<float2*>(ctx + (size_t)r0 * DD + c) =
            make_float2(O[nt][0] * inv0, O[nt][1] * inv0);
        *reinterpret_cast<float2*>(ctx + (size_t)(r0 + 8) * DD + c) =
            make_float2(O[nt][2] * inv1, O[nt][3] * inv1);
    }
}

// ---------------------------------------------------------------------------
extern "C" void kernel_launch(void* const* d_in, const int* in_sizes, int n_in,
                              void* d_out, int out_size)
{
    const float* x    = (const float*)d_in[0];
    const float* mask = (const float*)d_in[1];
    const float* Wq   = (const float*)d_in[2];
    const float* Wk   = (const float*)d_in[3];
    const float* Wv   = (const float*)d_in[4];
    const float* Wo   = (const float*)d_in[5];
    float* out = (float*)d_out;

    float *pQ, *pK, *pV, *pC;
    cudaGetSymbolAddress((void**)&pQ, g_Q);
    cudaGetSymbolAddress((void**)&pK, g_K);
    cudaGetSymbolAddress((void**)&pV, g_V);
    cudaGetSymbolAddress((void**)&pC, g_C);

    cudaFuncSetAttribute(gemm_qkv, cudaFuncAttributeMaxDynamicSharedMemorySize, GEMM_SMEM);
    cudaFuncSetAttribute(gemm_mma, cudaFuncAttributeMaxDynamicSharedMemorySize, GEMM_SMEM);
    cudaFuncSetAttribute(attn_mma, cudaFuncAttributeMaxDynamicSharedMemorySize, ATTN_SMEM);

    dim3 blk(256);

    dim3 qkvgrid(DD / 128, MTOT / 128, 3);   // (8, 32, 3)
    gemm_qkv<<<qkvgrid, blk, GEMM_SMEM>>>(x, Wq, Wk, Wv, pQ, pK, pV);

    dim3 agrid(SS / 128, HH, BB);            // (16, 16, 2)
    attn_mma<<<agrid, blk, ATTN_SMEM>>>(pQ, pK, pV, mask, pC);

    dim3 ggrid(DD / 128, MTOT / 128);        // (8, 32)
    gemm_mma<<<ggrid, blk, GEMM_SMEM>>>(pC, Wo, out, DD);
}

// round 8
// speedup vs baseline: 2.8816x; 1.0640x over previous
#include <cuda_runtime.h>
#include <cstdint>

// Problem constants
#define BB   2
#define SS   2048
#define DD   1024
#define HH   16
#define HD   64
#define MTOT (BB*SS)   // 4096
#define GK   1024

// Scratch (allocation-free: __device__ globals)
__device__ float g_Q[MTOT*DD];
__device__ float g_K[MTOT*DD];
__device__ float g_V[MTOT*DD];
__device__ float g_C[MTOT*DD];

// ---------------------------------------------------------------------------
// helpers
// ---------------------------------------------------------------------------
__device__ __forceinline__ uint32_t f2tf32(float f) {
    uint32_t r;
    asm("cvt.rna.tf32.f32 %0, %1;" : "=r"(r) : "f"(f));
    return r;
}
__device__ __forceinline__ void mma_tf32(float* c, const uint32_t* a, const uint32_t* b) {
    asm volatile(
        "mma.sync.aligned.m16n8k8.row.col.f32.tf32.tf32.f32 "
        "{%0,%1,%2,%3}, {%4,%5,%6,%7}, {%8,%9}, {%0,%1,%2,%3};"
        : "+f"(c[0]), "+f"(c[1]), "+f"(c[2]), "+f"(c[3])
        : "r"(a[0]), "r"(a[1]), "r"(a[2]), "r"(a[3]), "r"(b[0]), "r"(b[1]));
}
__device__ __forceinline__ uint32_t fbits(float f) { return __float_as_uint(f); }

__device__ __forceinline__ uint32_t smem_u32(const void* p) {
    uint32_t a;
    asm("{ .reg .u64 t; cvta.to.shared.u64 t, %1; cvt.u32.u64 %0, t; }"
        : "=r"(a) : "l"(p));
    return a;
}
#define LDSM_X4(r0, r1, r2, r3, addr) \
    asm volatile("ldmatrix.sync.aligned.m8n8.x4.shared.b16 {%0,%1,%2,%3}, [%4];" \
                 : "=r"(r0), "=r"(r1), "=r"(r2), "=r"(r3) : "r"(addr))
#define CP16(dst, src) \
    asm volatile("cp.async.ca.shared.global [%0], [%1], 16;" \
                 :: "r"(dst), "l"(src) : "memory")
#define CP_COMMIT() asm volatile("cp.async.commit_group;" ::: "memory")
#define CP_WAIT1()  asm volatile("cp.async.wait_group 1;" ::: "memory")
#define CP_WAIT0()  asm volatile("cp.async.wait_group 0;" ::: "memory")

// ===========================================================================
// GEMM: C[M,N] = A[M,K] @ W[N,K]^T, K=1024. mma.sync tf32, ldmatrix frags.
// CTA 128x128, BK=16, double-buffered, 2 CTAs/SM (40KB smem, <=128 regs).
// Smem stride 20 floats (80B): LDSM rows hit distinct 16B granules.
// ===========================================================================
#define GST    20
#define GTILE  (128*GST)          // floats per (A or B) tile
#define GTILEB (GTILE*4)          // bytes
#define GEMM_SMEM (4*GTILEB)      // 2 stages * (A+B) = 40960 B

__device__ __forceinline__
void gemm_body(const float* __restrict__ A, const float* __restrict__ W,
               float* __restrict__ C, int N, float* sm)
{
    const uint32_t sbase = smem_u32(sm);
    const int tid  = threadIdx.x;
    const int wid  = tid >> 5;
    const int lane = tid & 31;
    const int gp   = lane >> 2;
    const int tg   = lane & 3;
    const int wr   = wid & 1;      // warp m (0..1) -> 64 rows
    const int wc   = wid >> 1;     // warp n (0..3) -> 32 cols
    const int m0   = blockIdx.y << 7;
    const int n0   = blockIdx.x << 7;

    const float* Ap = A + (size_t)m0 * GK;
    const float* Wp = W + (size_t)n0 * GK;

    // staging map: g = tid + u*256 in [0,512): row = g>>2, c4 = (g&3)*4
    int srow[2], sc4[2];
#pragma unroll
    for (int u = 0; u < 2; u++) {
        int g = tid + (u << 8);
        srow[u] = g >> 2;
        sc4[u]  = (g & 3) << 2;
    }

    // ldmatrix lane address components
    const int aRow = wr * 64 + (lane & 15);       // + tm*16
    const int aSel = (lane >> 4) << 2;            // k col-block
    const int bRow = wc * 32 + ((lane >> 4) << 3) + (lane & 7);  // + p*16
    const int bSel = ((lane >> 3) & 1) << 2;

    float acc[16][4];
#pragma unroll
    for (int i = 0; i < 16; i++)
#pragma unroll
        for (int j = 0; j < 4; j++) acc[i][j] = 0.f;

    float4 pa[2], pb[2];
    // prologue: chunk 0
#pragma unroll
    for (int u = 0; u < 2; u++) {
        pa[u] = *reinterpret_cast<const float4*>(Ap + (size_t)srow[u] * GK + sc4[u]);
        pb[u] = *reinterpret_cast<const float4*>(Wp + (size_t)srow[u] * GK + sc4[u]);
    }
#pragma unroll
    for (int u = 0; u < 2; u++) {
        float* da = sm + srow[u] * GST + sc4[u];
        float* db = sm + GTILE + srow[u] * GST + sc4[u];
        da[0] = __uint_as_float(f2tf32(pa[u].x)); da[1] = __uint_as_float(f2tf32(pa[u].y));
        da[2] = __uint_as_float(f2tf32(pa[u].z)); da[3] = __uint_as_float(f2tf32(pa[u].w));
        db[0] = __uint_as_float(f2tf32(pb[u].x)); db[1] = __uint_as_float(f2tf32(pb[u].y));
        db[2] = __uint_as_float(f2tf32(pb[u].z)); db[3] = __uint_as_float(f2tf32(pb[u].w));
    }
    __syncthreads();

    const int NCH = GK / 16;   // 64
    for (int i = 0; i < NCH; i++) {
        const int b = i & 1;
        // prefetch next chunk to regs
        if (i + 1 < NCH) {
            const int kt = (i + 1) << 4;
#pragma unroll
            for (int u = 0; u < 2; u++) {
                pa[u] = *reinterpret_cast<const float4*>(Ap + (size_t)srow[u] * GK + kt + sc4[u]);
                pb[u] = *reinterpret_cast<const float4*>(Wp + (size_t)srow[u] * GK + kt + sc4[u]);
            }
        }

        const uint32_t sA = sbase + b * 2 * GTILEB;
        const uint32_t sB = sA + GTILEB;
#pragma unroll
        for (int kk = 0; kk < 2; kk++) {
            uint32_t af[4][4], bf[4][2];
#pragma unroll
            for (int tm = 0; tm < 4; tm++) {
                uint32_t addr = sA + (uint32_t)(((aRow + tm * 16) * GST + kk * 8 + aSel) * 4);
                LDSM_X4(af[tm][0], af[tm][1], af[tm][2], af[tm][3], addr);
            }
#pragma unroll
            for (int p = 0; p < 2; p++) {
                uint32_t addr = sB + (uint32_t)(((bRow + p * 16) * GST + kk * 8 + bSel) * 4);
                LDSM_X4(bf[2*p][0], bf[2*p][1], bf[2*p+1][0], bf[2*p+1][1], addr);
            }
#pragma unroll
            for (int tm = 0; tm < 4; tm++)
#pragma unroll
                for (int tn = 0; tn < 4; tn++)
                    mma_tf32(acc[tm * 4 + tn], af[tm], bf[tn]);
        }

        // stage next chunk into the other buffer
        if (i + 1 < NCH) {
            float* da0 = sm + (b ^ 1) * 2 * GTILE;
            float* db0 = da0 + GTILE;
#pragma unroll
            for (int u = 0; u < 2; u++) {
                float* da = da0 + srow[u] * GST + sc4[u];
                float* db = db0 + srow[u] * GST + sc4[u];
                da[0] = __uint_as_float(f2tf32(pa[u].x)); da[1] = __uint_as_float(f2tf32(pa[u].y));
                da[2] = __uint_as_float(f2tf32(pa[u].z)); da[3] = __uint_as_float(f2tf32(pa[u].w));
                db[0] = __uint_as_float(f2tf32(pb[u].x)); db[1] = __uint_as_float(f2tf32(pb[u].y));
                db[2] = __uint_as_float(f2tf32(pb[u].z)); db[3] = __uint_as_float(f2tf32(pb[u].w));
            }
        }
        __syncthreads();
    }

    // epilogue
#pragma unroll
    for (int tm = 0; tm < 4; tm++) {
        const int r = m0 + wr * 64 + tm * 16 + gp;
#pragma unroll
        for (int tn = 0; tn < 4; tn++) {
            const int c = n0 + wc * 32 + tn * 8 + 2 * tg;
            float* p0 = C + (size_t)r * N + c;
            float* p1 = C + (size_t)(r + 8) * N + c;
            *reinterpret_cast<float2*>(p0) = make_float2(acc[tm*4+tn][0], acc[tm*4+tn][1]);
            *reinterpret_cast<float2*>(p1) = make_float2(acc[tm*4+tn][2], acc[tm*4+tn][3]);
        }
    }
}

__global__ __launch_bounds__(256, 2)
void gemm_mma(const float* __restrict__ A, const float* __restrict__ W,
              float* __restrict__ C, int N)
{
    extern __shared__ float sm[];
    gemm_body(A, W, C, N, sm);
}

__global__ __launch_bounds__(256, 2)
void gemm_qkv(const float* __restrict__ x,
              const float* __restrict__ Wq, const float* __restrict__ Wk,
              const float* __restrict__ Wv,
              float* __restrict__ Qo, float* __restrict__ Ko, float* __restrict__ Vo)
{
    extern __shared__ float sm[];
    const int z = blockIdx.z;
    const float* W = (z == 0) ? Wq : (z == 1) ? Wk : Wv;
    float* C = (z == 0) ? Qo : (z == 1) ? Ko : Vo;
    gemm_body(x, W, C, DD, sm);
}

// ===========================================================================
// Flash attention (mma.sync tf32): Q frags in regs, cp.async K/V double-buffer,
// P in regs via shuffle remap, K fragments via ldmatrix.x4.
// ===========================================================================
#define KST 68
#define VST 72
#define KB0 0
#define VB0 (64*KST)
#define KB1 (VB0 + 64*VST)
#define VB1 (KB1 + 64*KST)
#define ATTN_SMEM ((VB1 + 64*VST)*4)   // 71680 B

__global__ __launch_bounds__(256, 1)
void attn_mma(const float* __restrict__ Q, const float* __restrict__ Kg,
              const float* __restrict__ V, const float* __restrict__ mask,
              float* __restrict__ ctx)
{
    extern __shared__ float sm[];
    const uint32_t sbase = smem_u32(sm);

    const int tid  = threadIdx.x;
    const int wid  = tid >> 5;
    const int lane = tid & 31;
    const int gp   = lane >> 2;
    const int tg   = lane & 3;

    const int qt = blockIdx.x;
    const int h  = blockIdx.y;
    const int b  = blockIdx.z;

    const int q0g  = b * SS + qt * 128;
    const int col0 = h * HD;
    const float scale = 0.03125f;

    int grow[4], gc4[4];
#pragma unroll
    for (int u = 0; u < 4; u++) {
        int g = tid + (u << 8);
        grow[u] = g >> 4;
        gc4[u]  = (g & 15) << 2;
    }

    // ldmatrix K address components
    const int kRowOff = ((lane >> 4) << 3) + (lane & 7);  // + p*16
    const int kSel    = ((lane >> 3) & 1) << 2;

    // ---- issue tile 0 loads
    {
        const int k0 = b * SS;
#pragma unroll
        for (int u = 0; u < 4; u++) {
            const float* ks = Kg + (size_t)(k0 + grow[u]) * DD + col0 + gc4[u];
            const float* vs = V  + (size_t)(k0 + grow[u]) * DD + col0 + gc4[u];
            CP16(sbase + (KB0 + grow[u] * KST + gc4[u]) * 4, ks);
            CP16(sbase + (VB0 + grow[u] * VST + gc4[u]) * 4, vs);
        }
        CP_COMMIT();
    }

    // ---- Q fragments in registers
    const int qm0 = wid * 16;
    uint32_t qf[8][4];
    {
        const float* q0p = Q + (size_t)(q0g + qm0 + gp) * DD + col0;
        const float* q1p = q0p + 8 * DD;
#pragma unroll
        for (int kk = 0; kk < 8; kk++) {
            const int c = kk * 8 + tg;
            qf[kk][0] = f2tf32(q0p[c]);
            qf[kk][1] = f2tf32(q1p[c]);
            qf[kk][2] = f2tf32(q0p[c + 4]);
            qf[kk][3] = f2tf32(q1p[c + 4]);
        }
    }

    float mprev0 = -1e30f, mprev1 = -1e30f;
    float lsum0 = 0.f, lsum1 = 0.f;
    float O[8][4];
#pragma unroll
    for (int i = 0; i < 8; i++)
#pragma unroll
        for (int j = 0; j < 4; j++) O[i][j] = 0.f;

    const float* mrow0 = mask + (size_t)(qt * 128 + qm0 + gp) * SS;
    const float* mrow1 = mrow0 + 8 * SS;
    const uint32_t qbase = lane & ~3u;

    const int NT = SS / 64;
    for (int t = 0; t < NT; t++) {
        const int bsel = t & 1;

        if (t + 1 < NT) {
            const int k1 = b * SS + (t + 1) * 64;
            const int kb = bsel ? KB0 : KB1;
            const int vb = bsel ? VB0 : VB1;
#pragma unroll
            for (int u = 0; u < 4; u++) {
                const float* ks = Kg + (size_t)(k1 + grow[u]) * DD + col0 + gc4[u];
                const float* vs = V  + (size_t)(k1 + grow[u]) * DD + col0 + gc4[u];
                CP16(sbase + (kb + grow[u] * KST + gc4[u]) * 4, ks);
                CP16(sbase + (vb + grow[u] * VST + gc4[u]) * 4, vs);
            }
            CP_COMMIT();
            CP_WAIT1();
        } else {
            CP_WAIT0();
        }
        __syncthreads();

        const uint32_t sK = sbase + (bsel ? KB1 : KB0) * 4;
        const float* Vs = sm + (bsel ? VB1 : VB0);

        // --- S = Q K^T (K frags via ldmatrix.x4)
        float sacc[8][4];
#pragma unroll
        for (int nt = 0; nt < 8; nt++)
#pragma unroll
            for (int j = 0; j < 4; j++) sacc[nt][j] = 0.f;

#pragma unroll
        for (int kk = 0; kk < 8; kk++) {
#pragma unroll
            for (int p = 0; p < 4; p++) {
                uint32_t b0[2], b1[2];
                uint32_t addr = sK + (uint32_t)(((p * 16 + kRowOff) * KST + kk * 8 + kSel) * 4);
                LDSM_X4(b0[0], b0[1], b1[0], b1[1], addr);
                mma_tf32(sacc[2*p],     qf[kk], b0);
                mma_tf32(sacc[2*p + 1], qf[kk], b1);
            }
        }

        // --- mask + scale, online softmax
        float mx0 = -1e30f, mx1 = -1e30f;
#pragma unroll
        for (int nt = 0; nt < 8; nt++) {
            const int kc = t * 64 + nt * 8 + 2 * tg;
            float2 mk0 = *reinterpret_cast<const float2*>(mrow0 + kc);
            float2 mk1 = *reinterpret_cast<const float2*>(mrow1 + kc);
            sacc[nt][0] = (sacc[nt][0] + mk0.x) * scale;
            sacc[nt][1] = (sacc[nt][1] + mk0.y) * scale;
            sacc[nt][2] = (sacc[nt][2] + mk1.x) * scale;
            sacc[nt][3] = (sacc[nt][3] + mk1.y) * scale;
            mx0 = fmaxf(mx0, fmaxf(sacc[nt][0], sacc[nt][1]));
            mx1 = fmaxf(mx1, fmaxf(sacc[nt][2], sacc[nt][3]));
        }
#pragma unroll
        for (int off = 1; off <= 2; off <<= 1) {
            mx0 = fmaxf(mx0, __shfl_xor_sync(0xffffffffu, mx0, off));
            mx1 = fmaxf(mx1, __shfl_xor_sync(0xffffffffu, mx1, off));
        }
        const float mn0 = fmaxf(mprev0, mx0);
        const float mn1 = fmaxf(mprev1, mx1);
        const float al0 = __expf(mprev0 - mn0);
        const float al1 = __expf(mprev1 - mn1);
        mprev0 = mn0; mprev1 = mn1;

        float rs0 = 0.f, rs1 = 0.f;
#pragma unroll
        for (int nt = 0; nt < 8; nt++) {
            sacc[nt][0] = __expf(sacc[nt][0] - mn0);
            sacc[nt][1] = __expf(sacc[nt][1] - mn0);
            sacc[nt][2] = __expf(sacc[nt][2] - mn1);
            sacc[nt][3] = __expf(sacc[nt][3] - mn1);
            rs0 += sacc[nt][0] + sacc[nt][1];
            rs1 += sacc[nt][2] + sacc[nt][3];
        }
#pragma unroll
        for (int off = 1; off <= 2; off <<= 1) {
            rs0 += __shfl_xor_sync(0xffffffffu, rs0, off);
            rs1 += __shfl_xor_sync(0xffffffffu, rs1, off);
        }
        lsum0 = lsum0 * al0 + rs0;
        lsum1 = lsum1 * al1 + rs1;

#pragma unroll
        for (int nt = 0; nt < 8; nt++) {
            O[nt][0] *= al0; O[nt][1] *= al0;
            O[nt][2] *= al1; O[nt][3] *= al1;
        }

        // --- O += P V ; P fragments via shuffle remap
#pragma unroll
        for (int kk = 0; kk < 8; kk++) {
            const uint32_t src0 = qbase + (tg >> 1);
            const uint32_t src2 = src0 + 2;
            float x0, x1;
            uint32_t af[4];
            x0 = __shfl_sync(0xffffffffu, sacc[kk][0], src0);
            x1 = __shfl_sync(0xffffffffu, sacc[kk][1], src0);
            af[0] = f2tf32((tg & 1) ? x1 : x0);
            x0 = __shfl_sync(0xffffffffu, sacc[kk][2], src0);
            x1 = __shfl_sync(0xffffffffu, sacc[kk][3], src0);
            af[1] = f2tf32((tg & 1) ? x1 : x0);
            x0 = __shfl_sync(0xffffffffu, sacc[kk][0], src2);
            x1 = __shfl_sync(0xffffffffu, sacc[kk][1], src2);
            af[2] = f2tf32((tg & 1) ? x1 : x0);
            x0 = __shfl_sync(0xffffffffu, sacc[kk][2], src2);
            x1 = __shfl_sync(0xffffffffu, sacc[kk][3], src2);
            af[3] = f2tf32((tg & 1) ? x1 : x0);

#pragma unroll
            for (int nt = 0; nt < 8; nt++) {
                uint32_t bf[2];
                const float* pv = Vs + (kk * 8 + tg) * VST + nt * 8 + gp;
                bf[0] = fbits(pv[0]);
                bf[1] = fbits(pv[4 * VST]);
                mma_tf32(O[nt], af, bf);
            }
        }
        __syncthreads();
    }

    // --- normalize + store
    const float inv0 = 1.0f / lsum0;
    const float inv1 = 1.0f / lsum1;
    const int r0 = q0g + qm0 + gp;
#pragma unroll
    for (int nt = 0; nt < 8; nt++) {
        const int c = col0 + nt * 8 + 2 * tg;
        *reinterpret_cast<float2*>(ctx + (size_t)r0 * DD + c) =
            make_float2(O[nt][0] * inv0, O[nt][1] * inv0);
        *reinterpret_cast<float2*>(ctx + (size_t)(r0 + 8) * DD + c) =
            make_float2(O[nt][2] * inv1, O[nt][3] * inv1);
    }
}

// ---------------------------------------------------------------------------
extern "C" void kernel_launch(void* const* d_in, const int* in_sizes, int n_in,
                              void* d_out, int out_size)
{
    const float* x    = (const float*)d_in[0];
    const float* mask = (const float*)d_in[1];
    const float* Wq   = (const float*)d_in[2];
    const float* Wk   = (const float*)d_in[3];
    const float* Wv   = (const float*)d_in[4];
    const float* Wo   = (const float*)d_in[5];
    float* out = (float*)d_out;

    float *pQ, *pK, *pV, *pC;
    cudaGetSymbolAddress((void**)&pQ, g_Q);
    cudaGetSymbolAddress((void**)&pK, g_K);
    cudaGetSymbolAddress((void**)&pV, g_V);
    cudaGetSymbolAddress((void**)&pC, g_C);

    cudaFuncSetAttribute(gemm_qkv, cudaFuncAttributeMaxDynamicSharedMemorySize, GEMM_SMEM);
    cudaFuncSetAttribute(gemm_mma, cudaFuncAttributeMaxDynamicSharedMemorySize, GEMM_SMEM);
    cudaFuncSetAttribute(attn_mma, cudaFuncAttributeMaxDynamicSharedMemorySize, ATTN_SMEM);

    dim3 blk(256);

    dim3 qkvgrid(DD / 128, MTOT / 128, 3);   // (8, 32, 3)
    gemm_qkv<<<qkvgrid, blk, GEMM_SMEM>>>(x, Wq, Wk, Wv, pQ, pK, pV);

    dim3 agrid(SS / 128, HH, BB);            // (16, 16, 2)
    attn_mma<<<agrid, blk, ATTN_SMEM>>>(pQ, pK, pV, mask, pC);

    dim3 ggrid(DD / 128, MTOT / 128);        // (8, 32)
    gemm_mma<<<ggrid, blk, GEMM_SMEM>>>(pC, Wo, out, DD);
}

// round 9
// speedup vs baseline: 3.1676x; 1.0992x over previous
#include <cuda_runtime.h>
#include <cstdint>

// Problem constants
#define BB   2
#define SS   2048
#define DD   1024
#define HH   16
#define HD   64
#define MTOT (BB*SS)   // 4096
#define GK   1024

// Scratch (allocation-free: __device__ globals)
__device__ float g_Q[MTOT*DD];
__device__ float g_K[MTOT*DD];
__device__ float g_V[MTOT*DD];
__device__ float g_C[MTOT*DD];
__device__ float g_X[MTOT*DD];     // tf32-truncated x
__device__ float g_Wq[DD*DD];      // tf32-truncated weights
__device__ float g_Wk[DD*DD];
__device__ float g_Wv[DD*DD];
__device__ float g_Wo[DD*DD];

// ---------------------------------------------------------------------------
// helpers
// ---------------------------------------------------------------------------
__device__ __forceinline__ uint32_t f2tf32(float f) {
    uint32_t r;
    asm("cvt.rna.tf32.f32 %0, %1;" : "=r"(r) : "f"(f));
    return r;
}
__device__ __forceinline__ void mma_tf32(float* c, const uint32_t* a, const uint32_t* b) {
    asm volatile(
        "mma.sync.aligned.m16n8k8.row.col.f32.tf32.tf32.f32 "
        "{%0,%1,%2,%3}, {%4,%5,%6,%7}, {%8,%9}, {%0,%1,%2,%3};"
        : "+f"(c[0]), "+f"(c[1]), "+f"(c[2]), "+f"(c[3])
        : "r"(a[0]), "r"(a[1]), "r"(a[2]), "r"(a[3]), "r"(b[0]), "r"(b[1]));
}
__device__ __forceinline__ uint32_t fbits(float f) { return __float_as_uint(f); }

__device__ __forceinline__ uint32_t smem_u32(const void* p) {
    uint32_t a;
    asm("{ .reg .u64 t; cvta.to.shared.u64 t, %1; cvt.u32.u64 %0, t; }"
        : "=r"(a) : "l"(p));
    return a;
}
#define LDSM_X4(r0, r1, r2, r3, addr) \
    asm volatile("ldmatrix.sync.aligned.m8n8.x4.shared.b16 {%0,%1,%2,%3}, [%4];" \
                 : "=r"(r0), "=r"(r1), "=r"(r2), "=r"(r3) : "r"(addr))
#define CP16(dst, src) \
    asm volatile("cp.async.ca.shared.global [%0], [%1], 16;" \
                 :: "r"(dst), "l"(src) : "memory")
#define CP_COMMIT() asm volatile("cp.async.commit_group;" ::: "memory")
#define CP_WAIT2()  asm volatile("cp.async.wait_group 2;" ::: "memory")
#define CP_WAIT1()  asm volatile("cp.async.wait_group 1;" ::: "memory")
#define CP_WAIT0()  asm volatile("cp.async.wait_group 0;" ::: "memory")

// ===========================================================================
// prep: tf32-truncate x and the 4 weight matrices (one pass, float4).
// 8 slices of 1M floats: 0-3 = x, 4..7 = Wq,Wk,Wv,Wo. grid 8192 x 256.
// ===========================================================================
__global__ __launch_bounds__(256)
void prep_cvt(const float* __restrict__ x,
              const float* __restrict__ wq, const float* __restrict__ wk,
              const float* __restrict__ wv, const float* __restrict__ wo,
              float* __restrict__ gx,
              float* __restrict__ gwq, float* __restrict__ gwk,
              float* __restrict__ gwv, float* __restrict__ gwo)
{
    const int slice = blockIdx.x >> 10;
    const int bx    = blockIdx.x & 1023;
    const size_t i4 = (size_t)bx * 256 + threadIdx.x;   // float4 idx in slice

    const float* src;
    float* dst;
    if (slice < 4) { src = x + (size_t)slice * 1048576; dst = gx + (size_t)slice * 1048576; }
    else if (slice == 4) { src = wq; dst = gwq; }
    else if (slice == 5) { src = wk; dst = gwk; }
    else if (slice == 6) { src = wv; dst = gwv; }
    else                 { src = wo; dst = gwo; }

    float4 v = reinterpret_cast<const float4*>(src)[i4];
    float4 o;
    o.x = __uint_as_float(f2tf32(v.x));
    o.y = __uint_as_float(f2tf32(v.y));
    o.z = __uint_as_float(f2tf32(v.z));
    o.w = __uint_as_float(f2tf32(v.w));
    reinterpret_cast<float4*>(dst)[i4] = o;
}

// ===========================================================================
// GEMM: C[M,N] = A[M,K] @ W[N,K]^T, K=1024, operands pre-truncated to tf32.
// CTA 128x128, BK=16, 4-stage cp.async ring, ldmatrix frags, 2 CTAs/SM.
// Smem stride 20 floats (80B = 5x16B): cp.async-aligned + LDSM conflict-free.
// ===========================================================================
#define NS     4
#define GST    20
#define GTILE  (128*GST)          // floats per (A or B) tile
#define GTILEB (GTILE*4)          // 10240 B
#define GSTAGEB (2*GTILEB)        // A+B per stage = 20480 B
#define GEMM_SMEM (NS*GSTAGEB)    // 81920 B

__device__ __forceinline__
void gemm_body(const float* __restrict__ A, const float* __restrict__ W,
               float* __restrict__ C, int N, char* smc)
{
    const uint32_t sbase = smem_u32(smc);
    const int tid  = threadIdx.x;
    const int wid  = tid >> 5;
    const int lane = tid & 31;
    const int gp   = lane >> 2;
    const int tg   = lane & 3;
    const int wr   = wid & 1;      // warp m (0..1) -> 64 rows
    const int wc   = wid >> 1;     // warp n (0..3) -> 32 cols
    const int m0   = blockIdx.y << 7;
    const int n0   = blockIdx.x << 7;

    const float* Ap = A + (size_t)m0 * GK;
    const float* Wp = W + (size_t)n0 * GK;

    // cp.async map: 512 granules per tile, 2 per thread
    int srow[2], sc4[2];
#pragma unroll
    for (int u = 0; u < 2; u++) {
        int g = tid + (u << 8);
        srow[u] = g >> 2;
        sc4[u]  = (g & 3) << 2;
    }

    // ldmatrix lane address components
    const int aRow = wr * 64 + (lane & 15);
    const int aSel = (lane >> 4) << 2;
    const int bRow = wc * 32 + ((lane >> 4) << 3) + (lane & 7);
    const int bSel = ((lane >> 3) & 1) << 2;

    float acc[16][4];
#pragma unroll
    for (int i = 0; i < 16; i++)
#pragma unroll
        for (int j = 0; j < 4; j++) acc[i][j] = 0.f;

    // prologue: chunks 0..NS-2
#pragma unroll
    for (int s = 0; s < NS - 1; s++) {
        const int kt = s << 4;
        const uint32_t stg = sbase + s * GSTAGEB;
#pragma unroll
        for (int u = 0; u < 2; u++) {
            CP16(stg + (uint32_t)((srow[u] * GST + sc4[u]) * 4),
                 Ap + (size_t)srow[u] * GK + kt + sc4[u]);
            CP16(stg + GTILEB + (uint32_t)((srow[u] * GST + sc4[u]) * 4),
                 Wp + (size_t)srow[u] * GK + kt + sc4[u]);
        }
        CP_COMMIT();
    }

    const int NCH = GK / 16;   // 64
    for (int i = 0; i < NCH; i++) {
        CP_WAIT2();            // chunk i complete (<=2 newer pending)
        __syncthreads();       // all warps see it; stage (i-1)%NS free

        // issue chunk i+NS-1 into stage (i+NS-1)%NS == (i-1)%NS
        if (i + NS - 1 < NCH) {
            const int kt = (i + NS - 1) << 4;
            const uint32_t stg = sbase + ((i + NS - 1) & (NS - 1)) * GSTAGEB;
#pragma unroll
            for (int u = 0; u < 2; u++) {
                CP16(stg + (uint32_t)((srow[u] * GST + sc4[u]) * 4),
                     Ap + (size_t)srow[u] * GK + kt + sc4[u]);
                CP16(stg + GTILEB + (uint32_t)((srow[u] * GST + sc4[u]) * 4),
                     Wp + (size_t)srow[u] * GK + kt + sc4[u]);
            }
        }
        CP_COMMIT();           // always (empty groups keep count uniform)

        const uint32_t sA = sbase + (i & (NS - 1)) * GSTAGEB;
        const uint32_t sB = sA + GTILEB;
#pragma unroll
        for (int kk = 0; kk < 2; kk++) {
            uint32_t af[4][4], bf[4][2];
#pragma unroll
            for (int tm = 0; tm < 4; tm++) {
                uint32_t addr = sA + (uint32_t)(((aRow + tm * 16) * GST + kk * 8 + aSel) * 4);
                LDSM_X4(af[tm][0], af[tm][1], af[tm][2], af[tm][3], addr);
            }
#pragma unroll
            for (int p = 0; p < 2; p++) {
                uint32_t addr = sB + (uint32_t)(((bRow + p * 16) * GST + kk * 8 + bSel) * 4);
                LDSM_X4(bf[2*p][0], bf[2*p][1], bf[2*p+1][0], bf[2*p+1][1], addr);
            }
#pragma unroll
            for (int tm = 0; tm < 4; tm++)
#pragma unroll
                for (int tn = 0; tn < 4; tn++)
                    mma_tf32(acc[tm * 4 + tn], af[tm], bf[tn]);
        }
    }

    // epilogue
#pragma unroll
    for (int tm = 0; tm < 4; tm++) {
        const int r = m0 + wr * 64 + tm * 16 + gp;
#pragma unroll
        for (int tn = 0; tn < 4; tn++) {
            const int c = n0 + wc * 32 + tn * 8 + 2 * tg;
            float* p0 = C + (size_t)r * N + c;
            float* p1 = C + (size_t)(r + 8) * N + c;
            *reinterpret_cast<float2*>(p0) = make_float2(acc[tm*4+tn][0], acc[tm*4+tn][1]);
            *reinterpret_cast<float2*>(p1) = make_float2(acc[tm*4+tn][2], acc[tm*4+tn][3]);
        }
    }
}

__global__ __launch_bounds__(256, 2)
void gemm_mma(const float* __restrict__ A, const float* __restrict__ W,
              float* __restrict__ C, int N)
{
    extern __shared__ char smc[];
    gemm_body(A, W, C, N, smc);
}

__global__ __launch_bounds__(256, 2)
void gemm_qkv(const float* __restrict__ x,
              const float* __restrict__ Wq, const float* __restrict__ Wk,
              const float* __restrict__ Wv,
              float* __restrict__ Qo, float* __restrict__ Ko, float* __restrict__ Vo)
{
    extern __shared__ char smc[];
    const int z = blockIdx.z;
    const float* W = (z == 0) ? Wq : (z == 1) ? Wk : Wv;
    float* C = (z == 0) ? Qo : (z == 1) ? Ko : Vo;
    gemm_body(x, W, C, DD, smc);
}

// ===========================================================================
// Flash attention (mma.sync tf32): Q frags in regs, cp.async K/V double-buffer,
// cp.async mask prefetch into smem, P in regs via shuffle remap, K via ldmatrix.
// ===========================================================================
#define KST 68
#define VST 72
#define MST 68
#define KB0 0
#define VB0 (64*KST)
#define KB1 (VB0 + 64*VST)
#define VB1 (KB1 + 64*KST)
#define MB  (VB1 + 64*VST)               // 17920 floats
#define ATTN_SMEM ((MB + 128*MST)*4)     // 106496 B

__global__ __launch_bounds__(256, 1)
void attn_mma(const float* __restrict__ Q, const float* __restrict__ Kg,
              const float* __restrict__ V, const float* __restrict__ mask,
              float* __restrict__ ctx)
{
    extern __shared__ float sm[];
    const uint32_t sbase = smem_u32(sm);

    const int tid  = threadIdx.x;
    const int wid  = tid >> 5;
    const int lane = tid & 31;
    const int gp   = lane >> 2;
    const int tg   = lane & 3;

    const int qt = blockIdx.x;
    const int h  = blockIdx.y;
    const int b  = blockIdx.z;

    const int q0g  = b * SS + qt * 128;
    const int col0 = h * HD;
    const float scale = 0.03125f;

    int grow[4], gc4[4];
#pragma unroll
    for (int u = 0; u < 4; u++) {
        int g = tid + (u << 8);
        grow[u] = g >> 4;
        gc4[u]  = (g & 15) << 2;
    }

    // ldmatrix K address components
    const int kRowOff = ((lane >> 4) << 3) + (lane & 7);
    const int kSel    = ((lane >> 3) & 1) << 2;

    // ---- issue K/V tile 0
    {
        const int k0 = b * SS;
#pragma unroll
        for (int u = 0; u < 4; u++) {
            const float* ks = Kg + (size_t)(k0 + grow[u]) * DD + col0 + gc4[u];
            const float* vs = V  + (size_t)(k0 + grow[u]) * DD + col0 + gc4[u];
            CP16(sbase + (KB0 + grow[u] * KST + gc4[u]) * 4, ks);
            CP16(sbase + (VB0 + grow[u] * VST + gc4[u]) * 4, vs);
        }
        CP_COMMIT();
    }

    // ---- Q fragments in registers
    const int qm0 = wid * 16;
    uint32_t qf[8][4];
    {
        const float* q0p = Q + (size_t)(q0g + qm0 + gp) * DD + col0;
        const float* q1p = q0p + 8 * DD;
#pragma unroll
        for (int kk = 0; kk < 8; kk++) {
            const int c = kk * 8 + tg;
            qf[kk][0] = f2tf32(q0p[c]);
            qf[kk][1] = f2tf32(q1p[c]);
            qf[kk][2] = f2tf32(q0p[c + 4]);
            qf[kk][3] = f2tf32(q1p[c + 4]);
        }
    }

    float mprev0 = -1e30f, mprev1 = -1e30f;
    float lsum0 = 0.f, lsum1 = 0.f;
    float O[8][4];
#pragma unroll
    for (int i = 0; i < 8; i++)
#pragma unroll
        for (int j = 0; j < 4; j++) O[i][j] = 0.f;

    const uint32_t qbase = lane & ~3u;
    const float* Ms0 = sm + MB + (qm0 + gp) * MST;
    const float* Ms1 = Ms0 + 8 * MST;
    const float* mtile0 = mask + (size_t)(qt * 128) * SS;

    const int NT = SS / 64;
    for (int t = 0; t < NT; t++) {
        const int bsel = t & 1;

        // issue mask tile t (committed BEFORE KV_{t+1} -> completes first)
        {
            const float* mb = mtile0 + t * 64;
#pragma unroll
            for (int u = 0; u < 8; u++) {
                int g = tid + (u << 8);
                int r = g >> 4;
                int c4 = (g & 15) << 2;
                CP16(sbase + (uint32_t)((MB + r * MST + c4) * 4),
                     mb + (size_t)r * SS + c4);
            }
            CP_COMMIT();
        }
        // issue K/V for t+1 into the other buffer
        if (t + 1 < NT) {
            const int k1 = b * SS + (t + 1) * 64;
            const int kb = bsel ? KB0 : KB1;
            const int vb = bsel ? VB0 : VB1;
#pragma unroll
            for (int u = 0; u < 4; u++) {
                const float* ks = Kg + (size_t)(k1 + grow[u]) * DD + col0 + gc4[u];
                const float* vs = V  + (size_t)(k1 + grow[u]) * DD + col0 + gc4[u];
                CP16(sbase + (kb + grow[u] * KST + gc4[u]) * 4, ks);
                CP16(sbase + (vb + grow[u] * VST + gc4[u]) * 4, vs);
            }
        }
        CP_COMMIT();   // always (possibly empty)

        CP_WAIT2();    // K/V tile t resident (mask_t, KV_{t+1} may pend)
        __syncthreads();

        const uint32_t sK = sbase + (bsel ? KB1 : KB0) * 4;
        const float* Vs = sm + (bsel ? VB1 : VB0);

        // --- S = Q K^T (K frags via ldmatrix.x4)
        float sacc[8][4];
#pragma unroll
        for (int nt = 0; nt < 8; nt++)
#pragma unroll
            for (int j = 0; j < 4; j++) sacc[nt][j] = 0.f;

#pragma unroll
        for (int kk = 0; kk < 8; kk++) {
#pragma unroll
            for (int p = 0; p < 4; p++) {
                uint32_t b0[2], b1[2];
                uint32_t addr = sK + (uint32_t)(((p * 16 + kRowOff) * KST + kk * 8 + kSel) * 4);
                LDSM_X4(b0[0], b0[1], b1[0], b1[1], addr);
                mma_tf32(sacc[2*p],     qf[kk], b0);
                mma_tf32(sacc[2*p + 1], qf[kk], b1);
            }
        }

        CP_WAIT1();    // mask tile t resident
        __syncthreads();

        // --- mask (from smem) + scale, online softmax
        float mx0 = -1e30f, mx1 = -1e30f;
#pragma unroll
        for (int nt = 0; nt < 8; nt++) {
            const int kc = nt * 8 + 2 * tg;
            float2 mk0 = *reinterpret_cast<const float2*>(Ms0 + kc);
            float2 mk1 = *reinterpret_cast<const float2*>(Ms1 + kc);
            sacc[nt][0] = (sacc[nt][0] + mk0.x) * scale;
            sacc[nt][1] = (sacc[nt][1] + mk0.y) * scale;
            sacc[nt][2] = (sacc[nt][2] + mk1.x) * scale;
            sacc[nt][3] = (sacc[nt][3] + mk1.y) * scale;
            mx0 = fmaxf(mx0, fmaxf(sacc[nt][0], sacc[nt][1]));
            mx1 = fmaxf(mx1, fmaxf(sacc[nt][2], sacc[nt][3]));
        }
#pragma unroll
        for (int off = 1; off <= 2; off <<= 1) {
            mx0 = fmaxf(mx0, __shfl_xor_sync(0xffffffffu, mx0, off));
            mx1 = fmaxf(mx1, __shfl_xor_sync(0xffffffffu, mx1, off));
        }
        const float mn0 = fmaxf(mprev0, mx0);
        const float mn1 = fmaxf(mprev1, mx1);
        const float al0 = __expf(mprev0 - mn0);
        const float al1 = __expf(mprev1 - mn1);
        mprev0 = mn0; mprev1 = mn1;

        float rs0 = 0.f, rs1 = 0.f;
#pragma unroll
        for (int nt = 0; nt < 8; nt++) {
            sacc[nt][0] = __expf(sacc[nt][0] - mn0);
            sacc[nt][1] = __expf(sacc[nt][1] - mn0);
            sacc[nt][2] = __expf(sacc[nt][2] - mn1);
            sacc[nt][3] = __expf(sacc[nt][3] - mn1);
            rs0 += sacc[nt][0] + sacc[nt][1];
            rs1 += sacc[nt][2] + sacc[nt][3];
        }
#pragma unroll
        for (int off = 1; off <= 2; off <<= 1) {
            rs0 += __shfl_xor_sync(0xffffffffu, rs0, off);
            rs1 += __shfl_xor_sync(0xffffffffu, rs1, off);
        }
        lsum0 = lsum0 * al0 + rs0;
        lsum1 = lsum1 * al1 + rs1;

#pragma unroll
        for (int nt = 0; nt < 8; nt++) {
            O[nt][0] *= al0; O[nt][1] *= al0;
            O[nt][2] *= al1; O[nt][3] *= al1;
        }

        // --- O += P V ; P fragments via shuffle remap
#pragma unroll
        for (int kk = 0; kk < 8; kk++) {
            const uint32_t src0 = qbase + (tg >> 1);
            const uint32_t src2 = src0 + 2;
            float x0, x1;
            uint32_t af[4];
            x0 = __shfl_sync(0xffffffffu, sacc[kk][0], src0);
            x1 = __shfl_sync(0xffffffffu, sacc[kk][1], src0);
            af[0] = f2tf32((tg & 1) ? x1 : x0);
            x0 = __shfl_sync(0xffffffffu, sacc[kk][2], src0);
            x1 = __shfl_sync(0xffffffffu, sacc[kk][3], src0);
            af[1] = f2tf32((tg & 1) ? x1 : x0);
            x0 = __shfl_sync(0xffffffffu, sacc[kk][0], src2);
            x1 = __shfl_sync(0xffffffffu, sacc[kk][1], src2);
            af[2] = f2tf32((tg & 1) ? x1 : x0);
            x0 = __shfl_sync(0xffffffffu, sacc[kk][2], src2);
            x1 = __shfl_sync(0xffffffffu, sacc[kk][3], src2);
            af[3] = f2tf32((tg & 1) ? x1 : x0);

#pragma unroll
            for (int nt = 0; nt < 8; nt++) {
                uint32_t bf[2];
                const float* pv = Vs + (kk * 8 + tg) * VST + nt * 8 + gp;
                bf[0] = fbits(pv[0]);
                bf[1] = fbits(pv[4 * VST]);
                mma_tf32(O[nt], af, bf);
            }
        }
        __syncthreads();   // protect KV_t + mask buffers before next-iter issues
    }

    // --- normalize + store context, pre-truncated for the Wo GEMM
    const float inv0 = 1.0f / lsum0;
    const float inv1 = 1.0f / lsum1;
    const int r0 = q0g + qm0 + gp;
#pragma unroll
    for (int nt = 0; nt < 8; nt++) {
        const int c = col0 + nt * 8 + 2 * tg;
        float2 v0 = make_float2(__uint_as_float(f2tf32(O[nt][0] * inv0)),
                                __uint_as_float(f2tf32(O[nt][1] * inv0)));
        float2 v1 = make_float2(__uint_as_float(f2tf32(O[nt][2] * inv1)),
                                __uint_as_float(f2tf32(O[nt][3] * inv1)));
        *reinterpret_cast<float2*>(ctx + (size_t)r0 * DD + c) = v0;
        *reinterpret_cast<float2*>(ctx + (size_t)(r0 + 8) * DD + c) = v1;
    }
}

// ---------------------------------------------------------------------------
extern "C" void kernel_launch(void* const* d_in, const int* in_sizes, int n_in,
                              void* d_out, int out_size)
{
    const float* x    = (const float*)d_in[0];
    const float* mask = (const float*)d_in[1];
    const float* Wq   = (const float*)d_in[2];
    const float* Wk   = (const float*)d_in[3];
    const float* Wv   = (const float*)d_in[4];
    const float* Wo   = (const float*)d_in[5];
    float* out = (float*)d_out;

    float *pQ, *pK, *pV, *pC, *pX, *pWq, *pWk, *pWv, *pWo;
    cudaGetSymbolAddress((void**)&pQ, g_Q);
    cudaGetSymbolAddress((void**)&pK, g_K);
    cudaGetSymbolAddress((void**)&pV, g_V);
    cudaGetSymbolAddress((void**)&pC, g_C);
    cudaGetSymbolAddress((void**)&pX, g_X);
    cudaGetSymbolAddress((void**)&pWq, g_Wq);
    cudaGetSymbolAddress((void**)&pWk, g_Wk);
    cudaGetSymbolAddress((void**)&pWv, g_Wv);
    cudaGetSymbolAddress((void**)&pWo, g_Wo);

    cudaFuncSetAttribute(gemm_qkv, cudaFuncAttributeMaxDynamicSharedMemorySize, GEMM_SMEM);
    cudaFuncSetAttribute(gemm_mma, cudaFuncAttributeMaxDynamicSharedMemorySize, GEMM_SMEM);
    cudaFuncSetAttribute(attn_mma, cudaFuncAttributeMaxDynamicSharedMemorySize, ATTN_SMEM);

    dim3 blk(256);

    prep_cvt<<<8192, blk>>>(x, Wq, Wk, Wv, Wo, pX, pWq, pWk, pWv, pWo);

    dim3 qkvgrid(DD / 128, MTOT / 128, 3);   // (8, 32, 3)
    gemm_qkv<<<qkvgrid, blk, GEMM_SMEM>>>(pX, pWq, pWk, pWv, pQ, pK, pV);

    dim3 agrid(SS / 128, HH, BB);            // (16, 16, 2)
    attn_mma<<<agrid, blk, ATTN_SMEM>>>(pQ, pK, pV, mask, pC);

    dim3 ggrid(DD / 128, MTOT / 128);        // (8, 32)
    gemm_mma<<<ggrid, blk, GEMM_SMEM>>>(pC, pWo, out, DD);
}